// round 16
// baseline (speedup 1.0000x reference)
#include <cuda_runtime.h>

namespace {

constexpr int NC  = 64;    // coarse samples (= fine samples)
constexpr int HID = 128;
constexpr int WPB = 4;     // warps per block; 2 rays per warp -> 8 rays/block

using u64 = unsigned long long;

__device__ __forceinline__ u64 f32x2_fma(u64 a, u64 b, u64 c) {
    u64 d;
    asm("fma.rn.f32x2 %0, %1, %2, %3;" : "=l"(d) : "l"(a), "l"(b), "l"(c));
    return d;
}
__device__ __forceinline__ u64 pack2(float lo, float hi) {
    u64 d;
    asm("mov.b64 %0, {%1, %2};" : "=l"(d) : "f"(lo), "f"(hi));
    return d;
}
__device__ __forceinline__ float2 unpack2(u64 v) {
    float2 r;
    asm("mov.b64 {%0, %1}, %2;" : "=f"(r.x), "=f"(r.y) : "l"(v));
    return r;
}

// Padded index for zs/outs: stride 9 per 8 entries -> conflict-free strided access.
__device__ __forceinline__ int pidx(int i) { return i + (i >> 3); }

struct alignas(16) RaySh {
    float4 ab2[HID / 2];            // {a_j, a_j+1, b_j, b_j+1} : 1024 B
    union {                         // lifetimes disjoint:
        float cdf[68];              //   cdf[0..64]
        struct {
            float  zs[144];         //   sorted z   (padded idx) : 576 B
            float4 outs[144];       //   sorted rgbs (padded idx): 2304 B
        } m;
    } u;                            // 2880 B
    unsigned ikc[NC];               // coarse int keys (ascending) : 256 B
    unsigned sk[NC];                // sorted fine int keys        : 256 B
    unsigned pmap[NC];              // fine idx -> sorted position : 256 B
};                                  // sizeof = 4672  (== 64 mod 128: the two
                                    // rays' ab2 arrays land on disjoint banks)

__device__ __forceinline__ unsigned make_key(float k, unsigned field) {
    return (__float_as_uint(k) & 0xFFFFFF80u) | field;
}

// MLP for 4 samples of one ray (each half-warp passes its own ab2 base).
__device__ __forceinline__ void mlp4(
    const ulonglong2* __restrict__ ab2u,
    const ulonglong2* __restrict__ w2u,
    u64 bx0, u64 by0, u64 bz0, u64 bw0,
    const float* z, float4* o)
{
    u64 zz[4];
#pragma unroll
    for (int i = 0; i < 4; i++) zz[i] = pack2(z[i], z[i]);
    u64 ax[4], ay[4], az[4], aw[4];
#pragma unroll
    for (int i = 0; i < 4; i++) { ax[i] = bx0; ay[i] = by0; az[i] = bz0; aw[i] = bw0; }

#pragma unroll 4
    for (int j2 = 0; j2 < HID / 2; j2++) {
        ulonglong2 p  = ab2u[j2];         // 1 wf: 2 rays' (aa,bb), disjoint banks
        ulonglong2 qa = w2u[2 * j2];      // broadcast: serves both rays
        ulonglong2 qb = w2u[2 * j2 + 1];  // broadcast: serves both rays
#pragma unroll
        for (int i = 0; i < 4; i++) {
            float2 t = unpack2(f32x2_fma(zz[i], p.y, p.x));
            u64 hh = pack2(fmaxf(t.x, 0.0f), fmaxf(t.y, 0.0f));
            ax[i] = f32x2_fma(hh, qa.x, ax[i]);
            ay[i] = f32x2_fma(hh, qa.y, ay[i]);
            az[i] = f32x2_fma(hh, qb.x, az[i]);
            aw[i] = f32x2_fma(hh, qb.y, aw[i]);
        }
    }
#pragma unroll
    for (int i = 0; i < 4; i++) {
        float2 v;
        v = unpack2(ax[i]); o[i].x = v.x + v.y;
        v = unpack2(ay[i]); o[i].y = v.x + v.y;
        v = unpack2(az[i]); o[i].z = v.x + v.y;
        v = unpack2(aw[i]); o[i].w = v.x + v.y;
    }
}

// Alpha compositing over K depth-sorted samples/lane within a 16-lane segment.
template <int K>
__device__ __forceinline__ float4 composite16(
    const float4* o, const float* z, const float* delta, float* w_out, int sl)
{
    float alpha[K], f[K];
    float prod = 1.0f;
#pragma unroll
    for (int i = 0; i < K; i++) {
        float sig = fmaxf(o[i].w, 0.0f);
        alpha[i] = 1.0f - __expf(-delta[i] * sig);
        f[i] = 1.0f - alpha[i] + 1e-10f;
        prod *= f[i];
    }
    float sc = prod;
#pragma unroll
    for (int off = 1; off < 16; off <<= 1) {
        float v = __shfl_up_sync(0xffffffffu, sc, off, 16);
        if (sl >= off) sc *= v;
    }
    float T = __shfl_up_sync(0xffffffffu, sc, 1, 16);
    if (sl == 0) T = 1.0f;

    float rx = 0.f, ry = 0.f, rz = 0.f, dd = 0.f;
#pragma unroll
    for (int i = 0; i < K; i++) {
        float w = alpha[i] * T;
        if (w_out) w_out[i] = w;
        rx = fmaf(w, o[i].x, rx);
        ry = fmaf(w, o[i].y, ry);
        rz = fmaf(w, o[i].z, rz);
        dd = fmaf(w, z[i],   dd);
        T *= f[i];
    }
#pragma unroll
    for (int off = 8; off > 0; off >>= 1) {
        rx += __shfl_xor_sync(0xffffffffu, rx, off, 16);
        ry += __shfl_xor_sync(0xffffffffu, ry, off, 16);
        rz += __shfl_xor_sync(0xffffffffu, rz, off, 16);
        dd += __shfl_xor_sync(0xffffffffu, dd, off, 16);
    }
    return make_float4(rx, ry, rz, dd);
}

// Compare-exchange on two registers.
__device__ __forceinline__ void csort(unsigned& a, unsigned& b, bool up) {
    unsigned lo = min(a, b), hi = max(a, b);
    a = up ? lo : hi;
    b = up ? hi : lo;
}
// Cross-lane bitonic exchange within 16-lane segment (lane xor mask m).
__device__ __forceinline__ void bmx(unsigned v[4], int m, bool up, int sl) {
    bool low = (sl & m) == 0;
    bool kmin = (low == up);
#pragma unroll
    for (int r = 0; r < 4; r++) {
        unsigned o = __shfl_xor_sync(0xffffffffu, v[r], m, 16);
        v[r] = kmin ? min(v[r], o) : max(v[r], o);
    }
}

// Count of sorted array elements (length 64) strictly less than key.
__device__ __forceinline__ int lower_bound64(const unsigned* __restrict__ a,
                                             unsigned key)
{
    int lo = 0;
#pragma unroll
    for (int step = 64; step >= 1; step >>= 1) {
        int nxt = lo + step;
        if (nxt <= 64 && a[nxt - 1] < key) lo = nxt;
    }
    return lo;
}

} // namespace

__global__ void __launch_bounds__(WPB * 32)
nerf_kernel(const float* __restrict__ rays,
            const float* __restrict__ u_coarse,
            const float* __restrict__ u_fine,
            const float* __restrict__ u_jitter,
            const float* __restrict__ W1,   // (3, 128)
            const float* __restrict__ b1,   // (128,)
            const float* __restrict__ W2,   // (128, 4)
            const float* __restrict__ b2,   // (4,)
            float* __restrict__ out)        // (R, 8)
{
    __shared__ float4 W2p[HID];     // pair-transposed layer-2 weights
    __shared__ float4 b2s;
    __shared__ RaySh rsall[2 * WPB];

    const int tid  = threadIdx.x;
    const int wid  = tid >> 5;
    const int lane = tid & 31;
    const int half = lane >> 4;     // which ray of the warp
    const int sl   = lane & 15;     // sub-lane within the ray's 16-lane segment
    const int ray  = blockIdx.x * (2 * WPB) + wid * 2 + half;

    if (tid < HID / 2) {
        float4 w0 = reinterpret_cast<const float4*>(W2)[2 * tid];
        float4 w1 = reinterpret_cast<const float4*>(W2)[2 * tid + 1];
        W2p[2 * tid]     = make_float4(w0.x, w1.x, w0.y, w1.y);
        W2p[2 * tid + 1] = make_float4(w0.z, w1.z, w0.w, w1.w);
    }
    if (tid == HID / 2) b2s = *reinterpret_cast<const float4*>(b2);
    __syncthreads();

    RaySh& rs = rsall[wid * 2 + half];
    const float* rp = rays + ray * 8;   // broadcast within each half
    const float ox = rp[0], oy = rp[1], oz = rp[2];
    const float dx = rp[3], dy = rp[4], dz = rp[5];
    const float nearv = rp[6], farv = rp[7];
    const float zscale = (farv - nearv) * (1.0f / NC);   // z = near + key*zscale

    // Per-ray layer-1 affine: lane handles 8 units (two float4 column groups)
    {
        const float4* W1_4 = reinterpret_cast<const float4*>(W1);
        const float4* b1_4 = reinterpret_cast<const float4*>(b1);
#pragma unroll
        for (int q = 0; q < 2; q++) {
            int i4 = 2 * sl + q;
            float4 w0 = W1_4[i4];
            float4 w1 = W1_4[32 + i4];
            float4 w2 = W1_4[64 + i4];
            float4 bb = b1_4[i4];
            float a0 = fmaf(ox, w0.x, fmaf(oy, w1.x, fmaf(oz, w2.x, bb.x)));
            float a1 = fmaf(ox, w0.y, fmaf(oy, w1.y, fmaf(oz, w2.y, bb.y)));
            float a2 = fmaf(ox, w0.z, fmaf(oy, w1.z, fmaf(oz, w2.z, bb.z)));
            float a3 = fmaf(ox, w0.w, fmaf(oy, w1.w, fmaf(oz, w2.w, bb.w)));
            float d0 = fmaf(dx, w0.x, fmaf(dy, w1.x, dz * w2.x));
            float d1 = fmaf(dx, w0.y, fmaf(dy, w1.y, dz * w2.y));
            float d2 = fmaf(dx, w0.z, fmaf(dy, w1.z, dz * w2.z));
            float d3 = fmaf(dx, w0.w, fmaf(dy, w1.w, dz * w2.w));
            rs.ab2[2 * i4]     = make_float4(a0, a1, d0, d1);
            rs.ab2[2 * i4 + 1] = make_float4(a2, a3, d2, d3);
        }
    }
    __syncwarp();

    const float4 b2v = b2s;
    const u64 bx0 = pack2(b2v.x, 0.0f);
    const u64 by0 = pack2(b2v.y, 0.0f);
    const u64 bz0 = pack2(b2v.z, 0.0f);
    const u64 bw0 = pack2(b2v.w, 0.0f);
    const ulonglong2* ab2u = reinterpret_cast<const ulonglong2*>(rs.ab2);
    const ulonglong2* w2u  = reinterpret_cast<const ulonglong2*>(W2p);

    // ---------------- Coarse pass: keys 4*sl .. 4*sl+3 ----------------
    float kc[4], zca[4], dca[4];
    {
        float4 uc = reinterpret_cast<const float4*>(u_coarse)[ray * 16 + sl];
        const float ucv[4] = {uc.x, uc.y, uc.z, uc.w};
#pragma unroll
        for (int i = 0; i < 4; i++) {
            kc[i] = (float)(4 * sl + i) + ucv[i];
            rs.ikc[4 * sl + i] = make_key(kc[i], 64u + 4 * sl + i);
            zca[i] = fmaf(kc[i], zscale, nearv);
        }
        float znxt = __shfl_down_sync(0xffffffffu, zca[0], 1, 16);
        if (sl == 15) znxt = farv;
        dca[0] = zca[1] - zca[0];
        dca[1] = zca[2] - zca[1];
        dca[2] = zca[3] - zca[2];
        dca[3] = znxt - zca[3];
    }
    float4 co[4];
    mlp4(ab2u, w2u, bx0, by0, bz0, bw0, zca, co);

    float wgt[4];
    float4 coarse = composite16<4>(co, zca, dca, wgt, sl);

    // ---------------- PDF / CDF over coarse weights ----------------
    {
        float p[4];
        float lt = 0.0f;
#pragma unroll
        for (int i = 0; i < 4; i++) { p[i] = wgt[i] + 1e-5f; lt += p[i]; }
        float tot = lt;
#pragma unroll
        for (int off = 8; off > 0; off >>= 1)
            tot += __shfl_xor_sync(0xffffffffu, tot, off, 16);
        float inv = 1.0f / tot;
        float s0 = p[0] * inv;
        float s1 = s0 + p[1] * inv;
        float s2 = s1 + p[2] * inv;
        float s3 = s2 + p[3] * inv;
        float sc = s3;
#pragma unroll
        for (int off = 1; off < 16; off <<= 1) {
            float v = __shfl_up_sync(0xffffffffu, sc, off, 16);
            if (sl >= off) sc += v;
        }
        float excl = __shfl_up_sync(0xffffffffu, sc, 1, 16);
        if (sl == 0) excl = 0.0f;
        if (sl == 0) rs.u.cdf[0] = 0.0f;
        rs.u.cdf[4 * sl + 1] = excl + s0;
        rs.u.cdf[4 * sl + 2] = excl + s1;
        rs.u.cdf[4 * sl + 3] = excl + s2;
        rs.u.cdf[4 * sl + 4] = excl + s3;
    }
    __syncwarp();

    // ------------- Fine sampling: searchsorted(right) - 1, + jitter -------------
    float kf[4];
    {
        float4 uf4 = reinterpret_cast<const float4*>(u_fine)[ray * 16 + sl];
        float4 uj4 = reinterpret_cast<const float4*>(u_jitter)[ray * 16 + sl];
        const float us[4] = {uf4.x, uf4.y, uf4.z, uf4.w};
        const float js[4] = {uj4.x, uj4.y, uj4.z, uj4.w};
#pragma unroll
        for (int k = 0; k < 4; k++) {
            int lo = 0, hi = 65;   // count of cdf entries <= u
            while (lo < hi) {
                int mid = (lo + hi) >> 1;
                if (rs.u.cdf[mid] <= us[k]) lo = mid + 1; else hi = mid;
            }
            int ind = max(lo - 1, 0);     // may be 64
            kf[k] = (float)ind + js[k];   // key in [0, 65)
        }
    }

    // ---- Fine MLP FIRST: its FFMA2 stream interleaves with the sort's serial
    // ---- shfl chain below (independent data; same straight-line region).
    float zn[4];
#pragma unroll
    for (int i = 0; i < 4; i++) zn[i] = fmaf(kf[i], zscale, nearv);
    float4 fo[4];
    mlp4(ab2u, w2u, bx0, by0, bz0, bw0, zn, fo);

    // -------- Bitonic sort of 64 fine int keys (4/lane, i = 4*sl + r) --------
    unsigned fk[4], v[4];
#pragma unroll
    for (int i = 0; i < 4; i++) {
        fk[i] = make_key(kf[i], (unsigned)(4 * sl + i));
        v[i] = fk[i];
    }
    {
        // k=2 (d=1, local; pair(0,1) up, pair(2,3) down)
        csort(v[0], v[1], true);  csort(v[2], v[3], false);
        // k=4: up = (sl&1)==0 ; d=2,1 local
        { bool up = (sl & 1) == 0;
          csort(v[0], v[2], up); csort(v[1], v[3], up);
          csort(v[0], v[1], up); csort(v[2], v[3], up); }
        // k=8: up = (sl&2)==0 ; d=4 (lane xor 1), then d=2,1 local
        { bool up = (sl & 2) == 0;
          bmx(v, 1, up, sl);
          csort(v[0], v[2], up); csort(v[1], v[3], up);
          csort(v[0], v[1], up); csort(v[2], v[3], up); }
        // k=16: up = (sl&4)==0 ; d=8,4 cross, d=2,1 local
        { bool up = (sl & 4) == 0;
          bmx(v, 2, up, sl); bmx(v, 1, up, sl);
          csort(v[0], v[2], up); csort(v[1], v[3], up);
          csort(v[0], v[1], up); csort(v[2], v[3], up); }
        // k=32: up = (sl&8)==0 ; d=16,8,4 cross, d=2,1 local
        { bool up = (sl & 8) == 0;
          bmx(v, 4, up, sl); bmx(v, 2, up, sl); bmx(v, 1, up, sl);
          csort(v[0], v[2], up); csort(v[1], v[3], up);
          csort(v[0], v[1], up); csort(v[2], v[3], up); }
        // k=64: up = true ; d=32,16,8,4 cross, d=2,1 local
        bmx(v, 8, true, sl); bmx(v, 4, true, sl);
        bmx(v, 2, true, sl); bmx(v, 1, true, sl);
        csort(v[0], v[2], true); csort(v[1], v[3], true);
        csort(v[0], v[1], true); csort(v[2], v[3], true);
    }
#pragma unroll
    for (int i = 0; i < 4; i++) {
        rs.sk[4 * sl + i] = v[i];
        rs.pmap[v[i] & 63u] = 4 * sl + i;
    }
    __syncwarp();

    // ------- Positions in merged order; scatter both record sets -------
    int posf[4];
#pragma unroll
    for (int i = 0; i < 4; i++)
        posf[i] = (int)rs.pmap[4 * sl + i] + lower_bound64(rs.ikc, fk[i]);
#pragma unroll
    for (int i = 0; i < 4; i++) {
        unsigned ick = make_key(kc[i], 64u + 4 * sl + i);
        int posc = 4 * sl + i + lower_bound64(rs.sk, ick);
        rs.u.m.zs[pidx(posc)]   = zca[i];
        rs.u.m.outs[pidx(posc)] = co[i];
    }
#pragma unroll
    for (int i = 0; i < 4; i++) {
        rs.u.m.zs[pidx(posf[i])]   = zn[i];
        rs.u.m.outs[pidx(posf[i])] = fo[i];
    }
    __syncwarp();

    // ---------------- Fine composite: samples 8*sl .. 8*sl+7 ----------------
    float zf[8], df[8];
    float4 go[8];
#pragma unroll
    for (int i = 0; i < 8; i++) {
        int p = pidx(8 * sl + i);
        zf[i] = rs.u.m.zs[p];
        go[i] = rs.u.m.outs[p];
    }
    {
        float znxt = __shfl_down_sync(0xffffffffu, zf[0], 1, 16);
        if (sl == 15) znxt = farv;
#pragma unroll
        for (int i = 0; i < 7; i++) df[i] = zf[i + 1] - zf[i];
        df[7] = znxt - zf[7];
    }
    float4 fine = composite16<8>(go, zf, df, nullptr, sl);

    if (sl == 0) {
        float4* op = reinterpret_cast<float4*>(out + ray * 8);
        op[0] = make_float4(coarse.x, coarse.y, coarse.z, coarse.w);
        op[1] = make_float4(fine.x, fine.y, fine.z, fine.w);
    }
}

extern "C" void kernel_launch(void* const* d_in, const int* in_sizes, int n_in,
                              void* d_out, int out_size)
{
    const float* rays     = (const float*)d_in[0];
    const float* u_coarse = (const float*)d_in[1];
    const float* u_fine   = (const float*)d_in[2];
    const float* u_jitter = (const float*)d_in[3];
    const float* W1       = (const float*)d_in[4];
    const float* b1       = (const float*)d_in[5];
    const float* W2       = (const float*)d_in[6];
    const float* b2       = (const float*)d_in[7];
    float* out            = (float*)d_out;

    static bool carveout_set = false;
    if (!carveout_set) {
        cudaFuncSetAttribute(nerf_kernel,
                             cudaFuncAttributePreferredSharedMemoryCarveout,
                             cudaSharedmemCarveoutMaxShared);
        carveout_set = true;
    }

    const int R = in_sizes[0] / 8;          // 16384
    const int blocks = R / (2 * WPB);       // 2048 (8 rays per block)
    nerf_kernel<<<blocks, WPB * 32>>>(rays, u_coarse, u_fine, u_jitter,
                                      W1, b1, W2, b2, out);
}

// round 17
// speedup vs baseline: 1.0655x; 1.0655x over previous
#include <cuda_runtime.h>

namespace {

constexpr int NC  = 64;    // coarse samples (= fine samples)
constexpr int HID = 128;
constexpr int WPB = 4;     // warps per block; 2 rays per warp -> 8 rays/block

using u64 = unsigned long long;

__device__ __forceinline__ u64 f32x2_fma(u64 a, u64 b, u64 c) {
    u64 d;
    asm("fma.rn.f32x2 %0, %1, %2, %3;" : "=l"(d) : "l"(a), "l"(b), "l"(c));
    return d;
}
__device__ __forceinline__ u64 pack2(float lo, float hi) {
    u64 d;
    asm("mov.b64 %0, {%1, %2};" : "=l"(d) : "f"(lo), "f"(hi));
    return d;
}
__device__ __forceinline__ float2 unpack2(u64 v) {
    float2 r;
    asm("mov.b64 {%0, %1}, %2;" : "=f"(r.x), "=f"(r.y) : "l"(v));
    return r;
}

// Padded index for zs/outs: stride 9 per 8 entries -> conflict-free strided access.
__device__ __forceinline__ int pidx(int i) { return i + (i >> 3); }

struct alignas(16) RaySh {
    float4 ab2[HID / 2];            // {a_j, a_j+1, b_j, b_j+1} : 1024 B
    union {                         // lifetimes disjoint:
        float cdf[68];              //   cdf[0..64]
        struct {
            float  zs[144];         //   sorted z   (padded idx) : 576 B
            float4 outs[144];       //   sorted rgbs (padded idx): 2304 B
        } m;
    } u;                            // 2880 B
    float    kcs[NC];               // coarse keys (kcs[j] in (j, j+1)) : 256 B
    unsigned sk[NC];                // sorted fine int keys             : 256 B
    unsigned pmap[NC];              // fine idx -> sorted position      : 256 B
};                                  // sizeof = 4672  (== 64 mod 128: the two
                                    // rays' ab2 arrays land on disjoint banks)

__device__ __forceinline__ unsigned make_key(float k, unsigned field) {
    return (__float_as_uint(k) & 0xFFFFFF80u) | field;
}

// MLP for 4 samples of one ray (each half-warp passes its own ab2 base).
__device__ __forceinline__ void mlp4(
    const ulonglong2* __restrict__ ab2u,
    const ulonglong2* __restrict__ w2u,
    u64 bx0, u64 by0, u64 bz0, u64 bw0,
    const float* z, float4* o)
{
    u64 zz[4];
#pragma unroll
    for (int i = 0; i < 4; i++) zz[i] = pack2(z[i], z[i]);
    u64 ax[4], ay[4], az[4], aw[4];
#pragma unroll
    for (int i = 0; i < 4; i++) { ax[i] = bx0; ay[i] = by0; az[i] = bz0; aw[i] = bw0; }

#pragma unroll 4
    for (int j2 = 0; j2 < HID / 2; j2++) {
        ulonglong2 p  = ab2u[j2];         // 1 wf: 2 rays' (aa,bb), disjoint banks
        ulonglong2 qa = w2u[2 * j2];      // broadcast: serves both rays
        ulonglong2 qb = w2u[2 * j2 + 1];  // broadcast: serves both rays
#pragma unroll
        for (int i = 0; i < 4; i++) {
            float2 t = unpack2(f32x2_fma(zz[i], p.y, p.x));
            u64 hh = pack2(fmaxf(t.x, 0.0f), fmaxf(t.y, 0.0f));
            ax[i] = f32x2_fma(hh, qa.x, ax[i]);
            ay[i] = f32x2_fma(hh, qa.y, ay[i]);
            az[i] = f32x2_fma(hh, qb.x, az[i]);
            aw[i] = f32x2_fma(hh, qb.y, aw[i]);
        }
    }
#pragma unroll
    for (int i = 0; i < 4; i++) {
        float2 v;
        v = unpack2(ax[i]); o[i].x = v.x + v.y;
        v = unpack2(ay[i]); o[i].y = v.x + v.y;
        v = unpack2(az[i]); o[i].z = v.x + v.y;
        v = unpack2(aw[i]); o[i].w = v.x + v.y;
    }
}

// Alpha compositing over K depth-sorted samples/lane within a 16-lane segment.
template <int K>
__device__ __forceinline__ float4 composite16(
    const float4* o, const float* z, const float* delta, float* w_out, int sl)
{
    float alpha[K], f[K];
    float prod = 1.0f;
#pragma unroll
    for (int i = 0; i < K; i++) {
        float sig = fmaxf(o[i].w, 0.0f);
        alpha[i] = 1.0f - __expf(-delta[i] * sig);
        f[i] = 1.0f - alpha[i] + 1e-10f;
        prod *= f[i];
    }
    float sc = prod;
#pragma unroll
    for (int off = 1; off < 16; off <<= 1) {
        float v = __shfl_up_sync(0xffffffffu, sc, off, 16);
        if (sl >= off) sc *= v;
    }
    float T = __shfl_up_sync(0xffffffffu, sc, 1, 16);
    if (sl == 0) T = 1.0f;

    float rx = 0.f, ry = 0.f, rz = 0.f, dd = 0.f;
#pragma unroll
    for (int i = 0; i < K; i++) {
        float w = alpha[i] * T;
        if (w_out) w_out[i] = w;
        rx = fmaf(w, o[i].x, rx);
        ry = fmaf(w, o[i].y, ry);
        rz = fmaf(w, o[i].z, rz);
        dd = fmaf(w, z[i],   dd);
        T *= f[i];
    }
#pragma unroll
    for (int off = 8; off > 0; off >>= 1) {
        rx += __shfl_xor_sync(0xffffffffu, rx, off, 16);
        ry += __shfl_xor_sync(0xffffffffu, ry, off, 16);
        rz += __shfl_xor_sync(0xffffffffu, rz, off, 16);
        dd += __shfl_xor_sync(0xffffffffu, dd, off, 16);
    }
    return make_float4(rx, ry, rz, dd);
}

// Compare-exchange on two registers.
__device__ __forceinline__ void csort(unsigned& a, unsigned& b, bool up) {
    unsigned lo = min(a, b), hi = max(a, b);
    a = up ? lo : hi;
    b = up ? hi : lo;
}
// Cross-lane bitonic exchange within 16-lane segment (lane xor mask m).
__device__ __forceinline__ void bmx(unsigned v[4], int m, bool up, int sl) {
    bool low = (sl & m) == 0;
    bool kmin = (low == up);
#pragma unroll
    for (int r = 0; r < 4; r++) {
        unsigned o = __shfl_xor_sync(0xffffffffu, v[r], m, 16);
        v[r] = kmin ? min(v[r], o) : max(v[r], o);
    }
}

// Count of sorted array elements (length 64) strictly less than key.
__device__ __forceinline__ int lower_bound64(const unsigned* __restrict__ a,
                                             unsigned key)
{
    int lo = 0;
#pragma unroll
    for (int step = 64; step >= 1; step >>= 1) {
        int nxt = lo + step;
        if (nxt <= 64 && a[nxt - 1] < key) lo = nxt;
    }
    return lo;
}

} // namespace

__global__ void __launch_bounds__(WPB * 32)
nerf_kernel(const float* __restrict__ rays,
            const float* __restrict__ u_coarse,
            const float* __restrict__ u_fine,
            const float* __restrict__ u_jitter,
            const float* __restrict__ W1,   // (3, 128)
            const float* __restrict__ b1,   // (128,)
            const float* __restrict__ W2,   // (128, 4)
            const float* __restrict__ b2,   // (4,)
            float* __restrict__ out)        // (R, 8)
{
    __shared__ float4 W2p[HID];     // pair-transposed layer-2 weights
    __shared__ float4 b2s;
    __shared__ RaySh rsall[2 * WPB];

    const int tid  = threadIdx.x;
    const int wid  = tid >> 5;
    const int lane = tid & 31;
    const int half = lane >> 4;     // which ray of the warp
    const int sl   = lane & 15;     // sub-lane within the ray's 16-lane segment
    const int ray  = blockIdx.x * (2 * WPB) + wid * 2 + half;

    if (tid < HID / 2) {
        float4 w0 = reinterpret_cast<const float4*>(W2)[2 * tid];
        float4 w1 = reinterpret_cast<const float4*>(W2)[2 * tid + 1];
        W2p[2 * tid]     = make_float4(w0.x, w1.x, w0.y, w1.y);
        W2p[2 * tid + 1] = make_float4(w0.z, w1.z, w0.w, w1.w);
    }
    if (tid == HID / 2) b2s = *reinterpret_cast<const float4*>(b2);
    __syncthreads();

    RaySh& rs = rsall[wid * 2 + half];
    const float* rp = rays + ray * 8;   // broadcast within each half
    const float ox = rp[0], oy = rp[1], oz = rp[2];
    const float dx = rp[3], dy = rp[4], dz = rp[5];
    const float nearv = rp[6], farv = rp[7];
    const float zscale = (farv - nearv) * (1.0f / NC);   // z = near + key*zscale

    // Per-ray layer-1 affine: lane handles 8 units (two float4 column groups)
    {
        const float4* W1_4 = reinterpret_cast<const float4*>(W1);
        const float4* b1_4 = reinterpret_cast<const float4*>(b1);
#pragma unroll
        for (int q = 0; q < 2; q++) {
            int i4 = 2 * sl + q;
            float4 w0 = W1_4[i4];
            float4 w1 = W1_4[32 + i4];
            float4 w2 = W1_4[64 + i4];
            float4 bb = b1_4[i4];
            float a0 = fmaf(ox, w0.x, fmaf(oy, w1.x, fmaf(oz, w2.x, bb.x)));
            float a1 = fmaf(ox, w0.y, fmaf(oy, w1.y, fmaf(oz, w2.y, bb.y)));
            float a2 = fmaf(ox, w0.z, fmaf(oy, w1.z, fmaf(oz, w2.z, bb.z)));
            float a3 = fmaf(ox, w0.w, fmaf(oy, w1.w, fmaf(oz, w2.w, bb.w)));
            float d0 = fmaf(dx, w0.x, fmaf(dy, w1.x, dz * w2.x));
            float d1 = fmaf(dx, w0.y, fmaf(dy, w1.y, dz * w2.y));
            float d2 = fmaf(dx, w0.z, fmaf(dy, w1.z, dz * w2.z));
            float d3 = fmaf(dx, w0.w, fmaf(dy, w1.w, dz * w2.w));
            rs.ab2[2 * i4]     = make_float4(a0, a1, d0, d1);
            rs.ab2[2 * i4 + 1] = make_float4(a2, a3, d2, d3);
        }
    }
    __syncwarp();

    const float4 b2v = b2s;
    const u64 bx0 = pack2(b2v.x, 0.0f);
    const u64 by0 = pack2(b2v.y, 0.0f);
    const u64 bz0 = pack2(b2v.z, 0.0f);
    const u64 bw0 = pack2(b2v.w, 0.0f);
    const ulonglong2* ab2u = reinterpret_cast<const ulonglong2*>(rs.ab2);
    const ulonglong2* w2u  = reinterpret_cast<const ulonglong2*>(W2p);

    // ---------------- Coarse pass: keys 4*sl .. 4*sl+3 ----------------
    float kc[4], zca[4], dca[4];
    {
        float4 uc = reinterpret_cast<const float4*>(u_coarse)[ray * 16 + sl];
        const float ucv[4] = {uc.x, uc.y, uc.z, uc.w};
#pragma unroll
        for (int i = 0; i < 4; i++) {
            kc[i] = (float)(4 * sl + i) + ucv[i];
            rs.kcs[4 * sl + i] = kc[i];
            zca[i] = fmaf(kc[i], zscale, nearv);
        }
        float znxt = __shfl_down_sync(0xffffffffu, zca[0], 1, 16);
        if (sl == 15) znxt = farv;
        dca[0] = zca[1] - zca[0];
        dca[1] = zca[2] - zca[1];
        dca[2] = zca[3] - zca[2];
        dca[3] = znxt - zca[3];
    }
    float4 co[4];
    mlp4(ab2u, w2u, bx0, by0, bz0, bw0, zca, co);

    float wgt[4];
    float4 coarse = composite16<4>(co, zca, dca, wgt, sl);

    // ---------------- PDF / CDF over coarse weights ----------------
    {
        float p[4];
        float lt = 0.0f;
#pragma unroll
        for (int i = 0; i < 4; i++) { p[i] = wgt[i] + 1e-5f; lt += p[i]; }
        float tot = lt;
#pragma unroll
        for (int off = 8; off > 0; off >>= 1)
            tot += __shfl_xor_sync(0xffffffffu, tot, off, 16);
        float inv = 1.0f / tot;
        float s0 = p[0] * inv;
        float s1 = s0 + p[1] * inv;
        float s2 = s1 + p[2] * inv;
        float s3 = s2 + p[3] * inv;
        float sc = s3;
#pragma unroll
        for (int off = 1; off < 16; off <<= 1) {
            float v = __shfl_up_sync(0xffffffffu, sc, off, 16);
            if (sl >= off) sc += v;
        }
        float excl = __shfl_up_sync(0xffffffffu, sc, 1, 16);
        if (sl == 0) excl = 0.0f;
        if (sl == 0) rs.u.cdf[0] = 0.0f;
        rs.u.cdf[4 * sl + 1] = excl + s0;
        rs.u.cdf[4 * sl + 2] = excl + s1;
        rs.u.cdf[4 * sl + 3] = excl + s2;
        rs.u.cdf[4 * sl + 4] = excl + s3;
    }
    __syncwarp();

    // ------------- Fine sampling: searchsorted(right) - 1, + jitter -------------
    float kf[4];
    {
        float4 uf4 = reinterpret_cast<const float4*>(u_fine)[ray * 16 + sl];
        float4 uj4 = reinterpret_cast<const float4*>(u_jitter)[ray * 16 + sl];
        const float us[4] = {uf4.x, uf4.y, uf4.z, uf4.w};
        const float js[4] = {uj4.x, uj4.y, uj4.z, uj4.w};
#pragma unroll
        for (int k = 0; k < 4; k++) {
            int lo = 0, hi = 65;   // count of cdf entries <= u
            while (lo < hi) {
                int mid = (lo + hi) >> 1;
                if (rs.u.cdf[mid] <= us[k]) lo = mid + 1; else hi = mid;
            }
            int ind = max(lo - 1, 0);     // may be 64
            kf[k] = (float)ind + js[k];   // key in [0, 65)
        }
    }

    // -------- Bitonic sort of 64 fine int keys (4/lane, i = 4*sl + r) --------
    unsigned fk[4], v[4];
#pragma unroll
    for (int i = 0; i < 4; i++) {
        fk[i] = make_key(kf[i], (unsigned)(4 * sl + i));
        v[i] = fk[i];
    }
    {
        // k=2 (d=1, local; pair(0,1) up, pair(2,3) down)
        csort(v[0], v[1], true);  csort(v[2], v[3], false);
        // k=4: up = (sl&1)==0 ; d=2,1 local
        { bool up = (sl & 1) == 0;
          csort(v[0], v[2], up); csort(v[1], v[3], up);
          csort(v[0], v[1], up); csort(v[2], v[3], up); }
        // k=8: up = (sl&2)==0 ; d=4 (lane xor 1), then d=2,1 local
        { bool up = (sl & 2) == 0;
          bmx(v, 1, up, sl);
          csort(v[0], v[2], up); csort(v[1], v[3], up);
          csort(v[0], v[1], up); csort(v[2], v[3], up); }
        // k=16: up = (sl&4)==0 ; d=8,4 cross, d=2,1 local
        { bool up = (sl & 4) == 0;
          bmx(v, 2, up, sl); bmx(v, 1, up, sl);
          csort(v[0], v[2], up); csort(v[1], v[3], up);
          csort(v[0], v[1], up); csort(v[2], v[3], up); }
        // k=32: up = (sl&8)==0 ; d=16,8,4 cross, d=2,1 local
        { bool up = (sl & 8) == 0;
          bmx(v, 4, up, sl); bmx(v, 2, up, sl); bmx(v, 1, up, sl);
          csort(v[0], v[2], up); csort(v[1], v[3], up);
          csort(v[0], v[1], up); csort(v[2], v[3], up); }
        // k=64: up = true ; d=32,16,8,4 cross, d=2,1 local
        bmx(v, 8, true, sl); bmx(v, 4, true, sl);
        bmx(v, 2, true, sl); bmx(v, 1, true, sl);
        csort(v[0], v[2], true); csort(v[1], v[3], true);
        csort(v[0], v[1], true); csort(v[2], v[3], true);
    }
#pragma unroll
    for (int i = 0; i < 4; i++) {
        rs.sk[4 * sl + i] = v[i];
        rs.pmap[v[i] & 63u] = 4 * sl + i;
    }
    __syncwarp();

    // ------- Fine positions: pmap + O(1) coarse count (kc[j] in (j, j+1)) -------
    // #coarse keys below fine key with bin b: all j <= b-1 qualify (kc[j] < j+1 <= b
    // <= kf), none with j >= b+1 (kc[j] > j >= b+1 > kf), so count = b +
    // (trunc(kc[b]) < trunc(kf)). Equal truncated keys sort fine-first, exactly
    // complementary to the posc side (ick low field 64+idx > fine's idx).
    int posf[4];
#pragma unroll
    for (int i = 0; i < 4; i++) {
        int bin = (int)kf[i];              // floor; kf in [0, 65)
        int cnt;
        if (bin >= NC) {
            cnt = NC;
        } else {
            unsigned tkc = __float_as_uint(rs.kcs[bin]) & 0xFFFFFF80u;
            unsigned tkf = __float_as_uint(kf[i])       & 0xFFFFFF80u;
            cnt = bin + (tkc < tkf);
        }
        posf[i] = (int)rs.pmap[4 * sl + i] + cnt;
    }

    // ------- Coarse positions via lower_bound on sorted fine keys; scatter -------
#pragma unroll
    for (int i = 0; i < 4; i++) {
        unsigned ick = make_key(kc[i], 64u + 4 * sl + i);
        int posc = 4 * sl + i + lower_bound64(rs.sk, ick);
        rs.u.m.zs[pidx(posc)]   = zca[i];
        rs.u.m.outs[pidx(posc)] = co[i];
    }

    // ---------------- MLP on the 64 NEW fine samples only ----------------
    float zn[4];
#pragma unroll
    for (int i = 0; i < 4; i++) zn[i] = fmaf(kf[i], zscale, nearv);
    float4 fo[4];
    mlp4(ab2u, w2u, bx0, by0, bz0, bw0, zn, fo);
#pragma unroll
    for (int i = 0; i < 4; i++) {
        rs.u.m.zs[pidx(posf[i])]   = zn[i];
        rs.u.m.outs[pidx(posf[i])] = fo[i];
    }
    __syncwarp();

    // ---------------- Fine composite: samples 8*sl .. 8*sl+7 ----------------
    float zf[8], df[8];
    float4 go[8];
#pragma unroll
    for (int i = 0; i < 8; i++) {
        int p = pidx(8 * sl + i);
        zf[i] = rs.u.m.zs[p];
        go[i] = rs.u.m.outs[p];
    }
    {
        float znxt = __shfl_down_sync(0xffffffffu, zf[0], 1, 16);
        if (sl == 15) znxt = farv;
#pragma unroll
        for (int i = 0; i < 7; i++) df[i] = zf[i + 1] - zf[i];
        df[7] = znxt - zf[7];
    }
    float4 fine = composite16<8>(go, zf, df, nullptr, sl);

    if (sl == 0) {
        float4* op = reinterpret_cast<float4*>(out + ray * 8);
        op[0] = make_float4(coarse.x, coarse.y, coarse.z, coarse.w);
        op[1] = make_float4(fine.x, fine.y, fine.z, fine.w);
    }
}

extern "C" void kernel_launch(void* const* d_in, const int* in_sizes, int n_in,
                              void* d_out, int out_size)
{
    const float* rays     = (const float*)d_in[0];
    const float* u_coarse = (const float*)d_in[1];
    const float* u_fine   = (const float*)d_in[2];
    const float* u_jitter = (const float*)d_in[3];
    const float* W1       = (const float*)d_in[4];
    const float* b1       = (const float*)d_in[5];
    const float* W2       = (const float*)d_in[6];
    const float* b2       = (const float*)d_in[7];
    float* out            = (float*)d_out;

    static bool carveout_set = false;
    if (!carveout_set) {
        cudaFuncSetAttribute(nerf_kernel,
                             cudaFuncAttributePreferredSharedMemoryCarveout,
                             cudaSharedmemCarveoutMaxShared);
        carveout_set = true;
    }

    const int R = in_sizes[0] / 8;          // 16384
    const int blocks = R / (2 * WPB);       // 2048 (8 rays per block)
    nerf_kernel<<<blocks, WPB * 32>>>(rays, u_coarse, u_fine, u_jitter,
                                      W1, b1, W2, b2, out);
}